// round 5
// baseline (speedup 1.0000x reference)
#include <cuda_runtime.h>
#include <cuda_bf16.h>

#define S 512
#define BB 512
#define T 64

// scratch (no allocations allowed)
__device__ float g_E[T * T];     // exp(transitions)
__device__ float g_den[BB];
__device__ float g_num[BB];

__device__ __forceinline__ float wsum(float v) {
#pragma unroll
    for (int o = 16; o; o >>= 1) v += __shfl_xor_sync(0xffffffffu, v, o);
    return v;
}

// ---------------------------------------------------------------------------
// Kernel 0: E = exp(transitions)
// ---------------------------------------------------------------------------
__global__ void crf_expE(const float* __restrict__ trans) {
    int i = blockIdx.x * blockDim.x + threadIdx.x;
    if (i < T * T) g_E[i] = __expf(trans[i]);
}

// ---------------------------------------------------------------------------
// Kernel 1: forward scan (denominator).
// One block (64 threads = 2 warps) per batch element; lane owns one state j.
// Probability vector kept normalized with a one-step lag: stored v satisfies
// alpha_j = C + log(v_j); the pending 1/U is folded into the next step so the
// cross-warp reduction is off the critical path. One __syncthreads per step.
// ---------------------------------------------------------------------------
__global__ void __launch_bounds__(64) crf_forward(
    const float* __restrict__ em,
    const int* __restrict__ mask,        // bool widened to int32 by harness
    const float* __restrict__ startT,
    const float* __restrict__ endT)
{
    __shared__ __align__(16) float ubuf[2][T];
    __shared__ float part[2][2];

    const int j    = threadIdx.x;     // state 0..63
    const int warp = j >> 5;
    const int lane = j & 31;
    const int b    = blockIdx.x;

    // E column for this state (64 registers)
    float Ecol[T];
#pragma unroll
    for (int i = 0; i < T; i++) Ecol[i] = g_E[i * T + j];

    const size_t bT     = (size_t)b * T;
    const size_t stride = (size_t)BB * T;

    // ---- init (s = 0) ----
    float u = __expf(startT[j] + em[bT + j]);
    int buf = 0;
    ubuf[0][j] = u;
    float ps = wsum(u);
    if (lane == 0) part[0][warp] = ps;
    __syncthreads();

    float U    = part[0][0] + part[0][1];
    float rinv = __fdividef(1.0f, U);
    float lu   = __logf(U);
    double C   = 0.0;   // accumulated log-normalizers

    // prefetch pipeline, distance 2
    float ea = em[stride * 1 + bT + j];
    int   ma = mask[1 * BB + b];
    float eb = em[stride * 2 + bT + j];
    int   mb = mask[2 * BB + b];

    for (int s = 1; s < S; s++) {
        int sp = (s + 2 < S) ? (s + 2) : (S - 1);
        float ec = em[stride * sp + bT + j];
        int   mc = mask[sp * BB + b];

        if (ma) {
            const float4* up = reinterpret_cast<const float4*>(ubuf[buf]);
            float t0 = 0.f, t1 = 0.f, t2 = 0.f, t3 = 0.f;
#pragma unroll
            for (int k = 0; k < 16; k++) {
                float4 v = up[k];
                t0 = fmaf(v.x, Ecol[4 * k],     t0);
                t1 = fmaf(v.y, Ecol[4 * k + 1], t1);
                t2 = fmaf(v.z, Ecol[4 * k + 2], t2);
                t3 = fmaf(v.w, Ecol[4 * k + 3], t3);
            }
            float t = (t0 + t1) + (t2 + t3);

            // apply lagged normalizer and emission
            u = t * rinv * __expf(ea);

            buf ^= 1;
            ubuf[buf][j] = u;
            float w = wsum(u);
            if (lane == 0) part[buf][warp] = w;
            C += (double)lu;            // previous normalizer now applied
            __syncthreads();

            U    = part[buf][0] + part[buf][1];
            rinv = __fdividef(1.0f, U);
            lu   = __logf(U);
        }
        // shift prefetch pipeline
        ea = eb; ma = mb;
        eb = ec; mb = mc;
    }

    // den = C + log( sum_j v_j * exp(end_j) )
    float v = u * __expf(endT[j]);
    float w = wsum(v);
    __syncthreads();                    // protect part[] from in-flight readers
    if (lane == 0) part[0][warp] = w;
    __syncthreads();
    if (j == 0) {
        float V = part[0][0] + part[0][1];
        g_den[b] = (float)(C + (double)__logf(V));
    }
}

// ---------------------------------------------------------------------------
// Kernel 2: numerator (tag-path score). One warp per batch element.
// tags and mask are int32 (harness converts int64/bool inputs to int32).
// ---------------------------------------------------------------------------
__global__ void __launch_bounds__(256) crf_num(
    const float* __restrict__ em,
    const int* __restrict__ tags,
    const int* __restrict__ mask,
    const float* __restrict__ startT,
    const float* __restrict__ endT,
    const float* __restrict__ trans)
{
    const int w    = threadIdx.x >> 5;
    const int lane = threadIdx.x & 31;
    const int b    = blockIdx.x * 8 + w;

    float acc = 0.0f;
    int cnt = 0;
    for (int s = lane; s < S; s += 32) {
        int t = tags[s * BB + b] & (T - 1);       // defensive clamp
        int m = mask[s * BB + b];
        cnt += (m ? 1 : 0);
        float e = em[(size_t)s * BB * T + (size_t)b * T + t];
        if (s == 0) {
            acc += startT[t] + e;
        } else if (m) {
            int tp = tags[(s - 1) * BB + b] & (T - 1);
            acc += trans[tp * T + t] + e;
        }
    }
    acc = wsum(acc);
#pragma unroll
    for (int o = 16; o; o >>= 1) cnt += __shfl_xor_sync(0xffffffffu, cnt, o);
    if (lane == 0) {
        int last = (cnt >= 1) ? (cnt - 1) : 0;    // guard against OOB
        int lt = tags[last * BB + b] & (T - 1);
        g_num[b] = acc + endT[lt];
    }
}

// ---------------------------------------------------------------------------
// Kernel 3: final mean reduction (fp64 accumulation)
// ---------------------------------------------------------------------------
__global__ void crf_final(float* __restrict__ out) {
    __shared__ double sh[512];
    int t = threadIdx.x;
    sh[t] = (double)g_num[t] - (double)g_den[t];
    __syncthreads();
#pragma unroll
    for (int o = 256; o > 0; o >>= 1) {
        if (t < o) sh[t] += sh[t + o];
        __syncthreads();
    }
    if (t == 0) out[0] = (float)(sh[0] * (1.0 / (double)BB));
}

// ---------------------------------------------------------------------------
extern "C" void kernel_launch(void* const* d_in, const int* in_sizes, int n_in,
                              void* d_out, int out_size)
{
    const float* em     = (const float*)d_in[0];
    const int*   tags   = (const int*)d_in[1];
    const int*   mask   = (const int*)d_in[2];
    const float* startT = (const float*)d_in[3];
    const float* endT   = (const float*)d_in[4];
    const float* trans  = (const float*)d_in[5];

    crf_expE<<<4, 1024>>>(trans);
    crf_forward<<<BB, 64>>>(em, mask, startT, endT);
    crf_num<<<BB / 8, 256>>>(em, tags, mask, startT, endT, trans);
    crf_final<<<1, 512>>>((float*)d_out);
}

// round 6
// speedup vs baseline: 1.0548x; 1.0548x over previous
#include <cuda_runtime.h>
#include <cuda_bf16.h>

#define S 512
#define BB 512
#define T 64

// scratch (no allocations allowed)
__device__ float g_den[BB];
__device__ float g_num[BB];
__device__ unsigned g_tick;

typedef unsigned long long u64;

// register-only packed f32x2 helpers (no memory asm)
__device__ __forceinline__ u64 ffma2(u64 a, u64 b, u64 c) {
    u64 d; asm("fma.rn.f32x2 %0, %1, %2, %3;" : "=l"(d) : "l"(a), "l"(b), "l"(c)); return d;
}
__device__ __forceinline__ u64 fadd2(u64 a, u64 b) {
    u64 d; asm("add.rn.f32x2 %0, %1, %2;" : "=l"(d) : "l"(a), "l"(b)); return d;
}
__device__ __forceinline__ u64 pack2(float x, float y) {
    u64 d; asm("mov.b64 %0, {%1, %2};" : "=l"(d) : "f"(x), "f"(y)); return d;
}
__device__ __forceinline__ float2 unpack2(u64 v) {
    float2 r; asm("mov.b64 {%0, %1}, %2;" : "=f"(r.x), "=f"(r.y) : "l"(v)); return r;
}
__device__ __forceinline__ float wsum(float v) {
#pragma unroll
    for (int o = 16; o; o >>= 1) v += __shfl_xor_sync(0xffffffffu, v, o);
    return v;
}

// ---------------------------------------------------------------------------
// Kernel 1: forward scan (denominator). One block (64 thr / 2 warps) / batch.
// Lane owns state j; its E-column lives in 32 packed-f32x2 registers.
// Probabilities are renormalized only every 8th step (fp32 has ~19 decades of
// headroom vs worst-case growth 270^8 ~ 3e19); the normalizer 1/U is applied
// lazily at the next step so its reduction+log never sits between two bars.
// exp(emission) is computed in the prefetch stage, off the critical path.
// ---------------------------------------------------------------------------
__global__ void __launch_bounds__(64) crf_forward(
    const float* __restrict__ em,
    const int* __restrict__ mask,        // bool widened to int32 by harness
    const float* __restrict__ trans,
    const float* __restrict__ startT,
    const float* __restrict__ endT)
{
    __shared__ __align__(16) float ubuf[2][T];
    __shared__ float part[2][2];

    const int j    = threadIdx.x;     // state 0..63
    const int warp = j >> 5;
    const int lane = j & 31;
    const int b    = blockIdx.x;

    if (b == 0 && j == 0) g_tick = 0;   // reset ticket for fused num+final

    // E column for this state, packed over i-pairs: Ecol2[p] = {E[2p][j], E[2p+1][j]}
    u64 Ecol2[T / 2];
#pragma unroll
    for (int p = 0; p < T / 2; p++) {
        Ecol2[p] = pack2(__expf(trans[(2 * p) * T + j]),
                         __expf(trans[(2 * p + 1) * T + j]));
    }

    const size_t bT     = (size_t)b * T;
    const size_t stride = (size_t)BB * T;

    // ---- init (s = 0): unnormalized, with pending normalizer ----
    float u = __expf(startT[j] + em[bT + j]);
    int buf = 0;
    ubuf[0][j] = u;
    float ps = wsum(u);
    if (lane == 0) part[0][warp] = ps;
    __syncthreads();

    float U0    = part[0][0] + part[0][1];
    float scale = __fdividef(1.0f, U0);   // pending: applied at next step
    float pend  = __logf(U0);
    double C    = 0.0;                    // applied log-normalizers

    // prefetch pipeline (distance 2) with exp(em) precomputed
    float xa = __expf(em[stride * 1 + bT + j]);
    int   ma = mask[1 * BB + b];
    float xb = __expf(em[stride * 2 + bT + j]);
    int   mb = mask[2 * BB + b];

    for (int s = 1; s < S; s++) {
        int sp = (s + 2 < S) ? (s + 2) : (S - 1);
        float xc = __expf(em[stride * sp + bT + j]);
        int   mc = mask[sp * BB + b];

        if (ma) {
            const ulonglong2* up = reinterpret_cast<const ulonglong2*>(ubuf[buf]);
            u64 a0 = 0, a1 = 0, a2 = 0, a3 = 0;
#pragma unroll
            for (int k = 0; k < 8; k++) {
                ulonglong2 v0 = up[2 * k];
                ulonglong2 v1 = up[2 * k + 1];
                a0 = ffma2(v0.x, Ecol2[4 * k],     a0);
                a1 = ffma2(v0.y, Ecol2[4 * k + 1], a1);
                a2 = ffma2(v1.x, Ecol2[4 * k + 2], a2);
                a3 = ffma2(v1.y, Ecol2[4 * k + 3], a3);
            }
            a0 = fadd2(a0, a1);
            a2 = fadd2(a2, a3);
            a0 = fadd2(a0, a2);
            float2 tt = unpack2(a0);
            float t = tt.x + tt.y;

            u = t * scale * xa;           // apply lazy normalizer + emission
            C += (double)pend;            // normalizer now applied
            pend = 0.0f;
            scale = 1.0f;

            buf ^= 1;
            ubuf[buf][j] = u;
            const bool dn = ((s & 7) == 0);
            if (dn) {                     // periodic renormalization setup
                float w = wsum(u);
                if (lane == 0) part[buf][warp] = w;
            }
            __syncthreads();
            if (dn) {
                float U = part[buf][0] + part[buf][1];
                scale = __fdividef(1.0f, U);
                pend  = __logf(U);
            }
        }
        xa = xb; ma = mb;
        xb = xc; mb = mc;
    }

    // den = C + log( sum_j u_j * exp(end_j) )   (pending normalizer unapplied
    // => u is unnormalized and C consistently excludes pend)
    float v = u * __expf(endT[j]);
    float w = wsum(v);
    __syncthreads();
    if (lane == 0) part[0][warp] = w;
    __syncthreads();
    if (j == 0) {
        float V = part[0][0] + part[0][1];
        g_den[b] = (float)(C + (double)__logf(V));
    }
}

// ---------------------------------------------------------------------------
// Kernel 2: numerator (tag-path score), one warp per batch element, fused
// with the final mean via a last-block ticket (deterministic: one block does
// the whole 512-element reduction in fixed order).
// ---------------------------------------------------------------------------
__global__ void __launch_bounds__(256) crf_num(
    const float* __restrict__ em,
    const int* __restrict__ tags,
    const int* __restrict__ mask,
    const float* __restrict__ startT,
    const float* __restrict__ endT,
    const float* __restrict__ trans,
    float* __restrict__ out)
{
    __shared__ double sh[256];
    __shared__ unsigned is_last;

    const int w    = threadIdx.x >> 5;
    const int lane = threadIdx.x & 31;
    const int b    = blockIdx.x * 8 + w;

    float acc = 0.0f;
    int cnt = 0;
    for (int s = lane; s < S; s += 32) {
        int t = tags[s * BB + b] & (T - 1);
        int m = mask[s * BB + b];
        cnt += (m ? 1 : 0);
        float e = em[(size_t)s * BB * T + (size_t)b * T + t];
        if (s == 0) {
            acc += startT[t] + e;
        } else if (m) {
            int tp = tags[(s - 1) * BB + b] & (T - 1);
            acc += trans[tp * T + t] + e;
        }
    }
    acc = wsum(acc);
#pragma unroll
    for (int o = 16; o; o >>= 1) cnt += __shfl_xor_sync(0xffffffffu, cnt, o);
    if (lane == 0) {
        int last = (cnt >= 1) ? (cnt - 1) : 0;
        int lt = tags[last * BB + b] & (T - 1);
        g_num[b] = acc + endT[lt];
    }

    // ---- last-block final reduction ----
    __syncthreads();
    __threadfence();
    if (threadIdx.x == 0) {
        unsigned old = atomicAdd(&g_tick, 1u);
        is_last = (old == gridDim.x - 1) ? 1u : 0u;
    }
    __syncthreads();
    if (is_last) {
        int t = threadIdx.x;
        double v = ((double)g_num[t]       - (double)g_den[t]) +
                   ((double)g_num[t + 256] - (double)g_den[t + 256]);
        sh[t] = v;
        __syncthreads();
#pragma unroll
        for (int o = 128; o > 0; o >>= 1) {
            if (t < o) sh[t] += sh[t + o];
            __syncthreads();
        }
        if (t == 0) out[0] = (float)(sh[0] * (1.0 / (double)BB));
    }
}

// ---------------------------------------------------------------------------
extern "C" void kernel_launch(void* const* d_in, const int* in_sizes, int n_in,
                              void* d_out, int out_size)
{
    const float* em     = (const float*)d_in[0];
    const int*   tags   = (const int*)d_in[1];
    const int*   mask   = (const int*)d_in[2];
    const float* startT = (const float*)d_in[3];
    const float* endT   = (const float*)d_in[4];
    const float* trans  = (const float*)d_in[5];

    crf_forward<<<BB, 64>>>(em, mask, trans, startT, endT);
    crf_num<<<BB / 8, 256>>>(em, tags, mask, startT, endT, trans, (float*)d_out);
}

// round 7
// speedup vs baseline: 1.6266x; 1.5421x over previous
#include <cuda_runtime.h>
#include <cuda_bf16.h>

#define S 512
#define BB 512
#define T 64

__device__ float g_den[BB];
__device__ float g_num[BB];
__device__ unsigned g_tick = 0;   // wraps via atomicInc; never reset

typedef unsigned long long u64;

__device__ __forceinline__ u64 ffma2(u64 a, u64 b, u64 c) {
    u64 d; asm("fma.rn.f32x2 %0, %1, %2, %3;" : "=l"(d) : "l"(a), "l"(b), "l"(c)); return d;
}
__device__ __forceinline__ u64 fadd2(u64 a, u64 b) {
    u64 d; asm("add.rn.f32x2 %0, %1, %2;" : "=l"(d) : "l"(a), "l"(b)); return d;
}
__device__ __forceinline__ u64 pack2(float x, float y) {
    u64 d; asm("mov.b64 %0, {%1, %2};" : "=l"(d) : "f"(x), "f"(y)); return d;
}
__device__ __forceinline__ float2 unpack2(u64 v) {
    float2 r; asm("mov.b64 {%0, %1}, %2;" : "=f"(r.x), "=f"(r.y) : "l"(v)); return r;
}
__device__ __forceinline__ float wsum(float v) {
#pragma unroll
    for (int o = 16; o; o >>= 1) v += __shfl_xor_sync(0xffffffffu, v, o);
    return v;
}

// ---------------------------------------------------------------------------
// Single fused kernel. One block (64 threads / 2 warps) per batch element.
//  Phase A: forward scan (denominator), chunked MLP=8 emission prefetch,
//           lazy normalizer applied at most once per 8 steps.
//  Phase B: numerator for the same batch (batched-MLP gathers).
//  Phase C: ticket-elected last block reduces mean(llh) into out[0].
// ---------------------------------------------------------------------------
__global__ void __launch_bounds__(64) crf_fused(
    const float* __restrict__ em,
    const int*   __restrict__ tags,     // int64 downgraded to int32 by harness
    const int*   __restrict__ mask,     // bool widened to int32 by harness
    const float* __restrict__ trans,
    const float* __restrict__ startT,
    const float* __restrict__ endT,
    float* __restrict__ out)
{
    __shared__ __align__(16) float ubuf[2][T];
    __shared__ float part[2][2];
    __shared__ float fin[2];
    __shared__ int   icnt[2];
    __shared__ unsigned is_last;

    const int j    = threadIdx.x;     // state / lane-role 0..63
    const int warp = j >> 5;
    const int lane = j & 31;
    const int b    = blockIdx.x;

    // E column for state j, packed over from-state pairs
    u64 Ecol2[T / 2];
#pragma unroll
    for (int p = 0; p < T / 2; p++) {
        Ecol2[p] = pack2(__expf(trans[(2 * p) * T + j]),
                         __expf(trans[(2 * p + 1) * T + j]));
    }

    const size_t bT     = (size_t)b * T;
    const size_t stride = (size_t)BB * T;

    // ---- Phase A: forward scan ----
    float u = __expf(startT[j] + em[bT + j]);
    int buf = 0;
    ubuf[0][j] = u;
    float ps = wsum(u);
    if (lane == 0) part[0][warp] = ps;
    __syncthreads();

    float U0    = part[0][0] + part[0][1];
    float scale = __fdividef(1.0f, U0);   // lazy: applied at next masked step
    float pend  = __logf(U0);
    double C    = 0.0;

    // preload chunk 0 (steps 1..8), MLP=8
    float xr[8]; int mr[8];
#pragma unroll
    for (int q = 0; q < 8; q++) {
        int s = 1 + q;
        xr[q] = em[stride * s + bT + j];
        mr[q] = mask[s * BB + b];
    }

    for (int c = 0; c < 64; c++) {
        // convert current chunk (data long since arrived)
        float xe[8]; int mm[8];
#pragma unroll
        for (int q = 0; q < 8; q++) { xe[q] = __expf(xr[q]); mm[q] = mr[q]; }
        // issue next chunk's 16 independent loads
        if (c < 63) {
#pragma unroll
            for (int q = 0; q < 8; q++) {
                int s = 9 + 8 * c + q;
                if (s < S) { xr[q] = em[stride * s + bT + j]; mr[q] = mask[s * BB + b]; }
            }
        }
#pragma unroll
        for (int q = 0; q < 8; q++) {
            int s = 1 + 8 * c + q;
            if (s >= S) break;                    // uniform (c==63,q==7 only)
            if (mm[q]) {
                const ulonglong2* up = reinterpret_cast<const ulonglong2*>(ubuf[buf]);
                u64 a0 = 0, a1 = 0, a2 = 0, a3 = 0;
#pragma unroll
                for (int k = 0; k < 8; k++) {
                    ulonglong2 v0 = up[2 * k];
                    ulonglong2 v1 = up[2 * k + 1];
                    a0 = ffma2(v0.x, Ecol2[4 * k],     a0);
                    a1 = ffma2(v0.y, Ecol2[4 * k + 1], a1);
                    a2 = ffma2(v1.x, Ecol2[4 * k + 2], a2);
                    a3 = ffma2(v1.y, Ecol2[4 * k + 3], a3);
                }
                a0 = fadd2(a0, a1);
                a2 = fadd2(a2, a3);
                a0 = fadd2(a0, a2);
                float2 tt = unpack2(a0);

                u = (tt.x + tt.y) * scale * xe[q];
                C += (double)pend;                // lazy normalizer applied
                pend = 0.0f; scale = 1.0f;

                buf ^= 1;
                ubuf[buf][j] = u;
                const bool dn = ((s & 7) == 0);   // once per chunk
                if (dn) {
                    float w = wsum(u);
                    if (lane == 0) part[buf][warp] = w;
                }
                __syncthreads();
                if (dn) {
                    float U = part[buf][0] + part[buf][1];
                    scale = __fdividef(1.0f, U);
                    pend  = __logf(U);
                }
            }
        }
    }

    // den = C + log( sum_j u_j * exp(end_j) )  (pending normalizer consistently excluded)
    {
        float v = u * __expf(endT[j]);
        float w = wsum(v);
        __syncthreads();
        if (lane == 0) part[0][warp] = w;
        __syncthreads();
        if (j == 0) {
            float V = part[0][0] + part[0][1];
            g_den[b] = (float)(C + (double)__logf(V));
        }
    }

    // ---- Phase B: numerator for batch b (thread j owns steps 8j..8j+7) ----
    {
        int tg[9];                 // tags[8j-1 .. 8j+7]
        int mk[8];
#pragma unroll
        for (int q = 0; q < 9; q++) {
            int s = 8 * j + q - 1;
            tg[q] = (s >= 0) ? (tags[s * BB + b] & (T - 1)) : 0;
        }
#pragma unroll
        for (int q = 0; q < 8; q++) mk[q] = mask[(8 * j + q) * BB + b];

        float acc = 0.0f;
        int cnt = 0;
#pragma unroll
        for (int q = 0; q < 8; q++) {
            int s = 8 * j + q;
            int t = tg[q + 1];
            cnt += (mk[q] ? 1 : 0);
            float e = em[stride * s + bT + t];
            if (s == 0)       acc += startT[t] + e;
            else if (mk[q])   acc += trans[tg[q] * T + t] + e;
        }
        acc = wsum(acc);
#pragma unroll
        for (int o = 16; o; o >>= 1) cnt += __shfl_xor_sync(0xffffffffu, cnt, o);
        if (lane == 0) { fin[warp] = acc; icnt[warp] = cnt; }
        __syncthreads();
        if (j == 0) {
            int total = icnt[0] + icnt[1];
            int last = (total >= 1) ? (total - 1) : 0;
            int lt = tags[last * BB + b] & (T - 1);
            g_num[b] = fin[0] + fin[1] + endT[lt];
        }
    }

    // ---- Phase C: last block reduces the mean ----
    __threadfence();
    __syncthreads();
    if (j == 0) {
        unsigned old;
        asm volatile("atom.global.inc.u32 %0, [%1], %2;"
                     : "=r"(old) : "l"(&g_tick), "r"((unsigned)(BB - 1)) : "memory");
        is_last = (old == BB - 1) ? 1u : 0u;
    }
    __syncthreads();
    if (is_last) {
        double v = 0.0;
#pragma unroll
        for (int k = 0; k < 8; k++) {
            int idx = j * 8 + k;
            v += (double)g_num[idx] - (double)g_den[idx];
        }
#pragma unroll
        for (int o = 16; o; o >>= 1) v += __shfl_xor_sync(0xffffffffu, v, o);
        if (lane == 0) ((volatile double*)ubuf)[warp] = v;   // reuse smem
        __syncthreads();
        if (j == 0) {
            double tot = ((volatile double*)ubuf)[0] + ((volatile double*)ubuf)[1];
            out[0] = (float)(tot * (1.0 / (double)BB));
        }
    }
}

// ---------------------------------------------------------------------------
extern "C" void kernel_launch(void* const* d_in, const int* in_sizes, int n_in,
                              void* d_out, int out_size)
{
    const float* em     = (const float*)d_in[0];
    const int*   tags   = (const int*)d_in[1];
    const int*   mask   = (const int*)d_in[2];
    const float* startT = (const float*)d_in[3];
    const float* endT   = (const float*)d_in[4];
    const float* trans  = (const float*)d_in[5];

    crf_fused<<<BB, 64>>>(em, tags, mask, trans, startT, endT, (float*)d_out);
}

// round 8
// speedup vs baseline: 1.6710x; 1.0273x over previous
#include <cuda_runtime.h>
#include <cuda_bf16.h>

#define S 512
#define BB 512
#define T 64

__device__ float g_den[BB];
__device__ float g_num[BB];
__device__ unsigned g_tick = 0;   // wraps via atomicInc; never reset

typedef unsigned long long u64;

__device__ __forceinline__ u64 ffma2(u64 a, u64 b, u64 c) {
    u64 d; asm("fma.rn.f32x2 %0, %1, %2, %3;" : "=l"(d) : "l"(a), "l"(b), "l"(c)); return d;
}
__device__ __forceinline__ u64 fadd2(u64 a, u64 b) {
    u64 d; asm("add.rn.f32x2 %0, %1, %2;" : "=l"(d) : "l"(a), "l"(b)); return d;
}
__device__ __forceinline__ u64 pack2(float x, float y) {
    u64 d; asm("mov.b64 %0, {%1, %2};" : "=l"(d) : "f"(x), "f"(y)); return d;
}
__device__ __forceinline__ float2 unpack2(u64 v) {
    float2 r; asm("mov.b64 {%0, %1}, %2;" : "=f"(r.x), "=f"(r.y) : "l"(v)); return r;
}
__device__ __forceinline__ float wsum(float v) {
#pragma unroll
    for (int o = 16; o; o >>= 1) v += __shfl_xor_sync(0xffffffffu, v, o);
    return v;
}

// ---------------------------------------------------------------------------
// One warp per batch element. Lane j owns states 2j and 2j+1; both E-columns
// live in 64 packed-f32x2 registers. The u vector is published duplicated
// ({u,u} per state) via one STS.128 per lane; the next step reads it as 32
// broadcast LDS.128. No block barrier anywhere in the scan — only __syncwarp.
// Renormalization every 8th step, applied lazily one step later.
// Block = 4 warps = 4 independent batches -> 1 warp per SMSP on 128 SMs.
// ---------------------------------------------------------------------------
__global__ void __launch_bounds__(128, 1) crf_fused(
    const float* __restrict__ em,
    const int*   __restrict__ tags,     // int64 downgraded to int32 by harness
    const int*   __restrict__ mask,     // bool widened to int32 by harness
    const float* __restrict__ trans,
    const float* __restrict__ startT,
    const float* __restrict__ endT,
    float* __restrict__ out)
{
    __shared__ __align__(16) float4 ubuf[4][2][32];   // [warp][buf][lane]
    __shared__ double dpart[4];
    __shared__ unsigned is_last;

    const int warp = threadIdx.x >> 5;
    const int j    = threadIdx.x & 31;      // lane; owns states 2j, 2j+1
    const int b    = blockIdx.x * 4 + warp;

    // E columns for states 2j, 2j+1 over all 64 from-states (128 regs)
    u64 Ecol2[T];
    {
        const float2* tr2 = reinterpret_cast<const float2*>(trans);
#pragma unroll
        for (int i = 0; i < T; i++) {
            float2 e = tr2[i * 32 + j];
            Ecol2[i] = pack2(__expf(e.x), __expf(e.y));
        }
    }

    const size_t bT     = (size_t)b * T;
    const size_t stride = (size_t)BB * T;
    const float2* em2base = reinterpret_cast<const float2*>(em + bT);
    const long em2stride = (long)(stride / 2);

    // ---- Phase A init (s = 0) ----
    float2 st0 = reinterpret_cast<const float2*>(startT)[j];
    float2 e0  = em2base[j];
    float u0 = __expf(st0.x + e0.x);
    float u1 = __expf(st0.y + e0.y);

    int buf = 0;
    ubuf[warp][0][j] = make_float4(u0, u0, u1, u1);
    __syncwarp();

    float U0    = wsum(u0 + u1);
    float scale = __fdividef(1.0f, U0);   // lazy: applied at next masked step
    float pend  = __logf(U0);
    double C    = 0.0;

    // preload chunk 0 (steps 1..8)
    float2 xr[8]; int mr[8];
#pragma unroll
    for (int q = 0; q < 8; q++) {
        int s = 1 + q;
        xr[q] = em2base[(long)s * em2stride + j];
        mr[q] = mask[s * BB + b];
    }

    for (int c = 0; c < 64; c++) {
        float2 xe[8]; int mm[8];
#pragma unroll
        for (int q = 0; q < 8; q++) {
            xe[q].x = __expf(xr[q].x);
            xe[q].y = __expf(xr[q].y);
            mm[q] = mr[q];
        }
        if (c < 63) {
#pragma unroll
            for (int q = 0; q < 8; q++) {
                int s = 9 + 8 * c + q;
                xr[q] = em2base[(long)s * em2stride + j];
                mr[q] = mask[s * BB + b];
            }
        }
#pragma unroll
        for (int q = 0; q < 8; q++) {
            int s = 1 + 8 * c + q;
            if (s >= S) break;                 // uniform (last chunk only)
            if (mm[q]) {
                const ulonglong2* up =
                    reinterpret_cast<const ulonglong2*>(ubuf[warp][buf]);
                u64 a0 = 0, a1 = 0, a2 = 0, a3 = 0;
#pragma unroll
                for (int k = 0; k < 16; k++) {
                    ulonglong2 v = up[2 * k];
                    ulonglong2 w = up[2 * k + 1];
                    a0 = ffma2(v.x, Ecol2[4 * k],     a0);
                    a1 = ffma2(v.y, Ecol2[4 * k + 1], a1);
                    a2 = ffma2(w.x, Ecol2[4 * k + 2], a2);
                    a3 = ffma2(w.y, Ecol2[4 * k + 3], a3);
                }
                a0 = fadd2(a0, a1);
                a2 = fadd2(a2, a3);
                a0 = fadd2(a0, a2);
                float2 tt = unpack2(a0);

                u0 = tt.x * scale * xe[q].x;
                u1 = tt.y * scale * xe[q].y;
                C += (double)pend;             // lazy normalizer applied
                pend = 0.0f; scale = 1.0f;

                buf ^= 1;
                ubuf[warp][buf][j] = make_float4(u0, u0, u1, u1);
                __syncwarp();
                if ((s & 7) == 0) {            // periodic renorm (lane-local)
                    float U = wsum(u0 + u1);
                    scale = __fdividef(1.0f, U);
                    pend  = __logf(U);
                }
            }
        }
    }

    // den = C + log( sum over states of u * exp(end) )
    {
        float2 en = reinterpret_cast<const float2*>(endT)[j];
        float v = u0 * __expf(en.x) + u1 * __expf(en.y);
        float V = wsum(v);
        if (j == 0) g_den[b] = (float)(C + (double)__logf(V));
    }

    // ---- Phase B: numerator (lane j owns steps 16j..16j+15, MLP gathers) ----
    {
        int tg[17]; int mk[16];
#pragma unroll
        for (int q = 0; q < 17; q++) {
            int s = 16 * j + q - 1;
            tg[q] = (s >= 0) ? (tags[s * BB + b] & (T - 1)) : 0;
        }
#pragma unroll
        for (int q = 0; q < 16; q++) mk[q] = mask[(16 * j + q) * BB + b];

        float acc = 0.0f;
        int cnt = 0;
#pragma unroll
        for (int q = 0; q < 16; q++) {
            int s = 16 * j + q;
            int t = tg[q + 1];
            cnt += (mk[q] ? 1 : 0);
            float e = em[stride * s + bT + t];
            if (s == 0)       acc += startT[t] + e;
            else if (mk[q])   acc += trans[tg[q] * T + t] + e;
        }
        acc = wsum(acc);
#pragma unroll
        for (int o = 16; o; o >>= 1) cnt += __shfl_xor_sync(0xffffffffu, cnt, o);
        if (j == 0) {
            int last = (cnt >= 1) ? (cnt - 1) : 0;
            int lt = tags[last * BB + b] & (T - 1);
            g_num[b] = acc + endT[lt];
        }
    }

    // ---- Phase C: ticket-elected last block computes the mean ----
    __threadfence();
    __syncthreads();
    if (threadIdx.x == 0) {
        unsigned old;
        asm volatile("atom.global.inc.u32 %0, [%1], %2;"
                     : "=r"(old) : "l"(&g_tick), "r"((unsigned)(gridDim.x - 1))
                     : "memory");
        is_last = (old == gridDim.x - 1) ? 1u : 0u;
    }
    __syncthreads();
    if (is_last) {
        int t = threadIdx.x;                 // 128 threads, 4 entries each
        double v = 0.0;
#pragma unroll
        for (int k = 0; k < 4; k++) {
            int idx = t * 4 + k;
            v += (double)g_num[idx] - (double)g_den[idx];
        }
#pragma unroll
        for (int o = 16; o; o >>= 1) v += __shfl_xor_sync(0xffffffffu, v, o);
        if (j == 0) dpart[warp] = v;
        __syncthreads();
        if (t == 0) {
            double tot = dpart[0] + dpart[1] + dpart[2] + dpart[3];
            out[0] = (float)(tot * (1.0 / (double)BB));
        }
    }
}

// ---------------------------------------------------------------------------
extern "C" void kernel_launch(void* const* d_in, const int* in_sizes, int n_in,
                              void* d_out, int out_size)
{
    const float* em     = (const float*)d_in[0];
    const int*   tags   = (const int*)d_in[1];
    const int*   mask   = (const int*)d_in[2];
    const float* startT = (const float*)d_in[3];
    const float* endT   = (const float*)d_in[4];
    const float* trans  = (const float*)d_in[5];

    crf_fused<<<BB / 4, 128>>>(em, tags, mask, trans, startT, endT, (float*)d_out);
}